// round 16
// baseline (speedup 1.0000x reference)
#include <cuda_runtime.h>
#include <cuda_bf16.h>
#include <mma.h>
#include <math.h>
#include <float.h>
#include <stdint.h>

using namespace nvcuda;

#define KD   64
#define NE   1024
#define NROW 65536
#define NZ   4194304

#define TC_MARGIN 1e-4f
#define LDZ 72      // bf16 elements per z-row in smem (pad: conflict-free ldmatrix, 32B-aligned tiles)
#define LDE 72      // bf16 elements per emb-row in smem
#define LDC 20      // fp32 elements per C-staging row

// ---------------- device scratch (no allocations allowed) ----------------
__device__ float          g_enorm[NE];
__device__ __nv_bfloat16  g_ehi[NE * KD];
__device__ __nv_bfloat16  g_elo[NE * KD];
__device__ int            g_counts[NE];
__device__ int            g_idx[NROW];
__device__ int            g_amb[NROW];
__device__ int            g_namb;
__device__ double         g_mse;
__device__ double         g_ed;

// smem layout for vq_mma (byte offsets, all 256-aligned)
#define S_ZHI 0                      // 128*72*2 = 18432
#define S_ZLO 18432                  // 18432
#define S_EHI 36864                  // 64*72*2 = 9216
#define S_ELO 46080                  // 9216
#define S_SA  55296                  // 128*4 = 512
#define S_SEN 55808                  // 1024*4 = 4096
#define S_CST 59904                  // 8*16*20*4 = 10240
#define S_TOTAL 70144

// ---------------- init: e-norms, bf16 hi/lo split of emb, zero scratch ----------------
// en bit-identical to jnp.sum(emb**2, axis=1): rounded square, sequential ascending adds.
__global__ void vq_init(const float* __restrict__ emb) {
    int t = blockIdx.x * blockDim.x + threadIdx.x;   // 0..1023
    const float* e = emb + (size_t)t * KD;
    float s = 0.f;
    #pragma unroll
    for (int k = 0; k < KD; k++) {
        float x = e[k];
        s = __fadd_rn(s, __fmul_rn(x, x));
        __nv_bfloat16 h = __float2bfloat16(x);
        float hf = __bfloat162float(h);
        g_ehi[t * KD + k] = h;
        g_elo[t * KD + k] = __float2bfloat16(x - hf);
    }
    g_enorm[t]  = s;
    g_counts[t] = 0;
    if (t == 0) { g_mse = 0.0; g_ed = 0.0; g_namb = 0; }
}

// ---------------- codebook pairwise distances (validated) ----------------
__global__ __launch_bounds__(256) void vq_ed(const float* __restrict__ emb) {
    __shared__ __align__(16) float Ei[64][65];
    __shared__ __align__(16) float Ej[64][65];
    const int tid = threadIdx.x;
    const int bi = blockIdx.x, bj = blockIdx.y;
    #pragma unroll
    for (int i = 0; i < 4; i++) {
        int idx = tid + i * 256;
        int r = idx >> 4, kq = idx & 15;
        float4 v = *reinterpret_cast<const float4*>(emb + (size_t)(bi * 64 + r) * KD + kq * 4);
        Ei[r][kq*4+0] = v.x; Ei[r][kq*4+1] = v.y; Ei[r][kq*4+2] = v.z; Ei[r][kq*4+3] = v.w;
        float4 w = *reinterpret_cast<const float4*>(emb + (size_t)(bj * 64 + r) * KD + kq * 4);
        Ej[r][kq*4+0] = w.x; Ej[r][kq*4+1] = w.y; Ej[r][kq*4+2] = w.z; Ej[r][kq*4+3] = w.w;
    }
    __syncthreads();
    const int il = tid & 63, jg = tid >> 6;
    float acc[16];
    #pragma unroll
    for (int jj = 0; jj < 16; jj++) acc[jj] = 0.f;
    for (int k = 0; k < KD; k++) {
        float a = Ei[il][k];
        #pragma unroll
        for (int jj = 0; jj < 16; jj++) acc[jj] = __fmaf_rn(a, Ej[jg*16+jj][k], acc[jj]);
    }
    float eni = g_enorm[bi * 64 + il];
    float s = 0.f;
    #pragma unroll
    for (int jj = 0; jj < 16; jj++) {
        int j = jg * 16 + jj;
        float t  = __fadd_rn(eni, g_enorm[bj * 64 + j]);
        float d2 = __fmaf_rn(-2.f, acc[jj], t);
        s += sqrtf(fmaxf(d2, 0.f));
    }
    #pragma unroll
    for (int off = 16; off > 0; off >>= 1) s += __shfl_down_sync(0xffffffffu, s, off);
    if ((tid & 31) == 0) atomicAdd(&g_ed, (double)s);
}

// ---------------- wmma screening pass: approx d for all 1024 codes, min1/idx1/min2 ----------------
// D = Zh*Eh + Zl*Eh + Zh*El (bf16 hi/lo 3-pass, fp32 accum). Error bound ~1.6e-5 << margin.
__global__ __launch_bounds__(256) void vq_mma(const float* __restrict__ z) {
    extern __shared__ __align__(256) char smem[];
    __nv_bfloat16* zhi = reinterpret_cast<__nv_bfloat16*>(smem + S_ZHI);
    __nv_bfloat16* zlo = reinterpret_cast<__nv_bfloat16*>(smem + S_ZLO);
    __nv_bfloat16* ehi = reinterpret_cast<__nv_bfloat16*>(smem + S_EHI);
    __nv_bfloat16* elo = reinterpret_cast<__nv_bfloat16*>(smem + S_ELO);
    float* sA  = reinterpret_cast<float*>(smem + S_SA);
    float* sEN = reinterpret_cast<float*>(smem + S_SEN);
    float* cst = reinterpret_cast<float*>(smem + S_CST);

    const int tid = threadIdx.x, wid = tid >> 5, lane = tid & 31;
    const int rowBase = blockIdx.x * 128;

    // stage all 1024 e-norms
    for (int i = tid; i < NE; i += 256) sEN[i] = g_enorm[i];

    // threads 0..127: own one z row — exact A (reference rounding: rounded square,
    // sequential ascending adds, no FMA) + bf16 hi/lo split into smem
    if (tid < 128) {
        const float4* zp = reinterpret_cast<const float4*>(z + (size_t)(rowBase + tid) * KD);
        float A = 0.f;
        #pragma unroll
        for (int q = 0; q < 16; q++) {
            float4 v = zp[q];
            float vv[4] = {v.x, v.y, v.z, v.w};
            #pragma unroll
            for (int j = 0; j < 4; j++) {
                float x = vv[j];
                A = __fadd_rn(A, __fmul_rn(x, x));
                __nv_bfloat16 h = __float2bfloat16(x);
                float hf = __bfloat162float(h);
                zhi[tid * LDZ + q * 4 + j] = h;
                zlo[tid * LDZ + q * 4 + j] = __float2bfloat16(x - hf);
            }
        }
        sA[tid] = A;
    }
    __syncthreads();

    // lane owns row (wid*16 + lane/2), cols (lane&1)*8..+8 of each 16-wide tile
    const int myrow = wid * 16 + (lane >> 1);
    const float Arow = sA[myrow];
    float* mycst = cst + wid * 16 * LDC;

    float m1 = FLT_MAX, m2 = FLT_MAX;
    int i1 = 0;

    wmma::fragment<wmma::matrix_a, 16, 16, 16, __nv_bfloat16, wmma::row_major> fah, fal;
    wmma::fragment<wmma::matrix_b, 16, 16, 16, __nv_bfloat16, wmma::col_major> fbh, fbl;
    wmma::fragment<wmma::accumulator, 16, 16, 16, float> fc;

    for (int ch = 0; ch < 16; ch++) {
        __syncthreads();            // prior chunk's fragment loads done
        // stage emb chunk (64 codes) hi/lo: [code][k] rows, ld=LDE
        {
            const uint32_t* gh = reinterpret_cast<const uint32_t*>(g_ehi) + ch * 2048;
            const uint32_t* gl = reinterpret_cast<const uint32_t*>(g_elo) + ch * 2048;
            for (int i = tid; i < 2048; i += 256) {
                int c = i >> 5, w = i & 31;     // code row, k-pair
                *reinterpret_cast<uint32_t*>(&ehi[c * LDE + w * 2]) = gh[i];
                *reinterpret_cast<uint32_t*>(&elo[c * LDE + w * 2]) = gl[i];
            }
        }
        __syncthreads();

        #pragma unroll
        for (int ns = 0; ns < 4; ns++) {        // 4 n-tiles of 16 codes
            wmma::fill_fragment(fc, 0.0f);
            #pragma unroll
            for (int k = 0; k < 4; k++) {       // K=64 in 4 steps of 16
                wmma::load_matrix_sync(fah, zhi + wid * 16 * LDZ + k * 16, LDZ);
                wmma::load_matrix_sync(fal, zlo + wid * 16 * LDZ + k * 16, LDZ);
                wmma::load_matrix_sync(fbh, ehi + ns * 16 * LDE + k * 16, LDE);
                wmma::load_matrix_sync(fbl, elo + ns * 16 * LDE + k * 16, LDE);
                wmma::mma_sync(fc, fah, fbh, fc);
                wmma::mma_sync(fc, fal, fbh, fc);
                wmma::mma_sync(fc, fah, fbl, fc);
            }
            wmma::store_matrix_sync(mycst, fc, LDC, wmma::mem_row_major);
            __syncwarp();
            const int code0 = ch * 64 + ns * 16 + (lane & 1) * 8;
            const float* rowp = mycst + (lane >> 1) * LDC + (lane & 1) * 8;
            #pragma unroll
            for (int j = 0; j < 8; j++) {
                int code = code0 + j;
                // d = fl(fl(A + en) - 2*dot): same rounding structure as reference
                float d = __fmaf_rn(-2.f, rowp[j], __fadd_rn(Arow, sEN[code]));
                if (d < m1) { m2 = m1; m1 = d; i1 = code; } else if (d < m2) { m2 = d; }
            }
            __syncwarp();           // scans done before next store overwrites staging
        }
    }

    // merge lane pairs (lane ^ 1): same row, disjoint code sets
    float o1 = __shfl_xor_sync(0xffffffffu, m1, 1);
    float o2 = __shfl_xor_sync(0xffffffffu, m2, 1);
    int   oi = __shfl_xor_sync(0xffffffffu, i1, 1);
    float M1; int I1;
    if (o1 < m1 || (o1 == m1 && oi < i1)) { M1 = o1; I1 = oi; } else { M1 = m1; I1 = i1; }
    float M2 = fminf(fmaxf(m1, o1), fminf(m2, o2));   // 2nd smallest of union
    if ((lane & 1) == 0) {
        int grow = rowBase + myrow;
        g_idx[grow] = I1;
        if (M2 - M1 <= TC_MARGIN) {          // ambiguous (incl. all exact ties) -> exact rescore
            int p = atomicAdd(&g_namb, 1);
            g_amb[p] = grow;
        }
    }
}

// ---------------- exact rescore of ambiguous rows (bit-identical reference numerics) ----------------
__global__ __launch_bounds__(256) void vq_rescore(const float* __restrict__ z,
                                                  const float* __restrict__ emb) {
    __shared__ float zs[16][64];
    __shared__ int   amb_s[16];
    __shared__ float sv[16][16];
    __shared__ int   si[16][16];
    const int tid = threadIdx.x;
    const int namb = g_namb;
    for (int base = blockIdx.x * 16; base < namb; base += gridDim.x * 16) {
        int n = namb - base; if (n > 16) n = 16;
        if (tid < 16) amb_s[tid] = (tid < n) ? g_amb[base + tid] : 0;
        __syncthreads();
        #pragma unroll
        for (int i = 0; i < 4; i++) {
            int x = tid + i * 256, r = x >> 6, k = x & 63;
            if (r < n) zs[r][k] = z[(size_t)amb_s[r] * KD + k];
        }
        __syncthreads();
        int r = tid >> 4, g = tid & 15;          // 16 rows x 16 code-strips of 64
        if (r < n) {
            float A = 0.f;
            for (int k = 0; k < KD; k++) { float x = zs[r][k]; A = __fadd_rn(A, __fmul_rn(x, x)); }
            float bv = FLT_MAX; int bi = NE;
            for (int c = 0; c < 64; c++) {
                int code = g * 64 + c;
                const float4* ep = reinterpret_cast<const float4*>(emb + (size_t)code * KD);
                float s = 0.f;
                #pragma unroll
                for (int q = 0; q < 16; q++) {
                    float4 e4 = ep[q];
                    s = __fmaf_rn(zs[r][q*4+0], e4.x, s);
                    s = __fmaf_rn(zs[r][q*4+1], e4.y, s);
                    s = __fmaf_rn(zs[r][q*4+2], e4.z, s);
                    s = __fmaf_rn(zs[r][q*4+3], e4.w, s);
                }
                float d = __fmaf_rn(-2.f, s, __fadd_rn(A, g_enorm[code]));
                if (d < bv) { bv = d; bi = code; }
            }
            sv[r][g] = bv; si[r][g] = bi;
        }
        __syncthreads();
        if (tid < n) {
            float bv = FLT_MAX; int bi = NE;
            #pragma unroll
            for (int g2 = 0; g2 < 16; g2++) {
                float v = sv[tid][g2]; int i2 = si[tid][g2];
                if (v < bv || (v == bv && i2 < bi)) { bv = v; bi = i2; }
            }
            g_idx[amb_s[tid]] = bi;
        }
        __syncthreads();
    }
}

// ---------------- outputs: indices, counts, gather + STE + MSE ----------------
__global__ __launch_bounds__(256) void vq_out(const float* __restrict__ z,
                                              const float* __restrict__ emb,
                                              float* __restrict__ out) {
    __shared__ int ridx[128];
    const int tid = threadIdx.x, rowBase = blockIdx.x * 128;
    if (tid < 128) {
        int bi = g_idx[rowBase + tid];
        ridx[tid] = bi;
        out[1 + NZ + 1 + rowBase + tid] = (float)bi;
        atomicAdd(&g_counts[bi], 1);
    }
    __syncthreads();
    float msum = 0.f;
    #pragma unroll
    for (int i = 0; i < 32; i++) {
        int flat = i * 256 + tid;
        int r = flat >> 6, k = flat & 63;
        int b = ridx[r];
        float ev = __ldg(emb + (size_t)b * KD + k);
        float zv = __ldg(z + (size_t)(rowBase + r) * KD + k);
        float dd = __fadd_rn(ev, -zv);
        msum = __fmaf_rn(dd, dd, msum);
        out[1 + (size_t)(rowBase + r) * KD + k] = __fadd_rn(zv, dd);
    }
    #pragma unroll
    for (int off = 16; off > 0; off >>= 1) msum += __shfl_down_sync(0xffffffffu, msum, off);
    if ((tid & 31) == 0) atomicAdd(&g_mse, (double)msum);
}

// ---------------- final scalars (validated) ----------------
__global__ void vq_final(float* __restrict__ out) {
    __shared__ float warpsum[32];
    int tid = threadIdx.x;
    float p = (float)g_counts[tid] * (1.0f / 65536.0f);
    float s = p * logf(p + 1e-10f);
    #pragma unroll
    for (int off = 16; off > 0; off >>= 1) s += __shfl_down_sync(0xffffffffu, s, off);
    if ((tid & 31) == 0) warpsum[tid >> 5] = s;
    __syncthreads();
    if (tid < 32) {
        float v = warpsum[tid];
        #pragma unroll
        for (int off = 16; off > 0; off >>= 1) v += __shfl_down_sync(0xffffffffu, v, off);
        if (tid == 0) {
            float perp  = expf(-v);
            float mse   = (float)(g_mse * (1.0 / (double)NZ));
            float meant = (float)(g_ed * 0.5 / (1024.0 * 1024.0));
            float eloss = expf(-meant * 10.0f);
            out[0]      = 1.25f * mse + eloss;
            out[1 + NZ] = perp;
        }
    }
}

extern "C" void kernel_launch(void* const* d_in, const int* in_sizes, int n_in,
                              void* d_out, int out_size) {
    const float* z   = (const float*)d_in[0];
    const float* emb = (const float*)d_in[1];
    float* out = (float*)d_out;
    (void)in_sizes; (void)n_in; (void)out_size;

    cudaFuncSetAttribute(vq_mma, cudaFuncAttributeMaxDynamicSharedMemorySize, S_TOTAL);

    vq_init<<<8, 128>>>(emb);
    vq_ed<<<dim3(16, 16), 256>>>(emb);
    vq_mma<<<512, 256, S_TOTAL>>>(z);
    vq_rescore<<<256, 256>>>(z, emb);
    vq_out<<<512, 256>>>(z, emb, out);
    vq_final<<<1, 1024>>>(out);
}